// round 16
// baseline (speedup 1.0000x reference)
#include <cuda_runtime.h>
#include <cuda_bf16.h>
#include <cstdint>

typedef unsigned long long ull;

// ---------------- scratch (no allocation allowed) ----------------
__device__ float g_mods[16 * 5 * 512];         // [b][layer][gam|bet]
__device__ float g_loss[16];                   // per-b summed loss
// transposed + bf16 hi/lo split weights:
// [layer][plane hi/lo][n=256][k=256] bf16  -> 4 * 2 * 131072 bytes
__device__ unsigned char g_B[4 * 2 * 131072];

// ---------------- helpers ----------------
__device__ __forceinline__ uint32_t smem_u32(const void* p) {
    uint32_t a;
    asm("{ .reg .u64 t; cvta.to.shared.u64 t, %1; cvt.u32.u64 %0, t; }"
        : "=r"(a) : "l"(p));
    return a;
}
__device__ __forceinline__ void cp16(void* dst, const void* src) {
    unsigned s = smem_u32(dst);
    asm volatile("cp.async.ca.shared.global [%0], [%1], 16;" :: "r"(s), "l"(src));
}
__device__ __forceinline__ void ldm_x4(uint32_t* r, const void* p) {
    uint32_t a = smem_u32(p);
    asm volatile("ldmatrix.sync.aligned.m8n8.x4.shared.b16 {%0,%1,%2,%3}, [%4];"
                 : "=r"(r[0]), "=r"(r[1]), "=r"(r[2]), "=r"(r[3]) : "r"(a));
}
__device__ __forceinline__ void mma16816(float* c, const uint32_t* a, const uint32_t* b) {
    asm volatile(
        "mma.sync.aligned.m16n8k16.row.col.f32.bf16.bf16.f32 "
        "{%0,%1,%2,%3}, {%4,%5,%6,%7}, {%8,%9}, {%0,%1,%2,%3};"
        : "+f"(c[0]), "+f"(c[1]), "+f"(c[2]), "+f"(c[3])
        : "r"(a[0]), "r"(a[1]), "r"(a[2]), "r"(a[3]), "r"(b[0]), "r"(b[1]));
}
__device__ __forceinline__ uint32_t pack_split(float x0, float x1, uint32_t& lo_out) {
    __nv_bfloat16 h0 = __float2bfloat16(x0);
    __nv_bfloat16 h1 = __float2bfloat16(x1);
    __nv_bfloat16 l0 = __float2bfloat16(x0 - __bfloat162float(h0));
    __nv_bfloat16 l1 = __float2bfloat16(x1 - __bfloat162float(h1));
    lo_out = ((uint32_t)__bfloat16_as_ushort(l1) << 16) | __bfloat16_as_ushort(l0);
    return ((uint32_t)__bfloat16_as_ushort(h1) << 16) | __bfloat16_as_ushort(h0);
}

// =================================================================
// Kernel 1: fused weight-prep (blocks 0..127) + residual VQ + FiLM
// mods (blocks 128..143). 1024 threads.
// =================================================================
__global__ __launch_bounds__(1024)
void prep_vq_kernel(const int* __restrict__ lidx,
                    const float* __restrict__ latents,
                    const float* __restrict__ emb,
                    const float* __restrict__ mod_W,
                    const float* __restrict__ mod_b,
                    const float* __restrict__ Whg) {
    if (blockIdx.x < 128) {
        const int i = blockIdx.x * 1024 + threadIdx.x;   // 131072 total
        const int layer = i >> 15;
        const int kp    = (i >> 8) & 127;
        const int n     = i & 255;
        const int k     = kp * 2;
        float w0 = Whg[(size_t)layer * 65536 + (size_t)k * 256 + n];
        float w1 = Whg[(size_t)layer * 65536 + (size_t)(k + 1) * 256 + n];
        uint32_t lo, hi = pack_split(w0, w1, lo);
        unsigned char* base = g_B + (size_t)layer * 262144;
        *reinterpret_cast<uint32_t*>(base + n * 512 + k * 2)          = hi;
        *reinterpret_cast<uint32_t*>(base + 131072 + n * 512 + k * 2) = lo;
        return;
    }

    __shared__ float r[256];
    __shared__ float q[256];
    __shared__ float wsc[32];
    __shared__ int   wci[32];
    __shared__ float s_d, s_r2;
    __shared__ int   s_c;

    const int b = blockIdx.x - 128, t = threadIdx.x;
    const int lane = t & 31, wid = t >> 5;

    if (t < 256) {
        const float* lp = latents + (size_t)lidx[b] * 1024;
        float z = lp[t] + lp[256 + t] + lp[512 + t] + lp[768 + t];
        r[t] = z; q[t] = 0.f;
    }
    __syncthreads();

    if (wid == 0) {
        float rz = 0.f;
        #pragma unroll
        for (int j = 0; j < 8; ++j) { float v = r[lane * 8 + j]; rz = fmaf(v, v, rz); }
        #pragma unroll
        for (int o = 16; o; o >>= 1) rz += __shfl_xor_sync(~0u, rz, o);
        if (lane == 0) s_r2 = rz;
    }
    float loss = 0.f;
    __syncthreads();

    for (int s = 0; s < 4; ++s) {
        float4 rj0 = reinterpret_cast<const float4*>(r)[lane * 2];
        float4 rj1 = reinterpret_cast<const float4*>(r)[lane * 2 + 1];
        float best = -3.4e38f;
        int   bi   = 0;
        const int c0 = wid * 32;
        #pragma unroll 8
        for (int i = 0; i < 32; ++i) {
            const int c = c0 + i;
            const float4* E4 = reinterpret_cast<const float4*>(emb)
                               + (size_t)(s * 1024 + c) * 64 + lane * 2;
            float4 e0 = E4[0], e1 = E4[1];
            float p = e0.x * rj0.x + e0.y * rj0.y + e0.z * rj0.z + e0.w * rj0.w
                    + e1.x * rj1.x + e1.y * rj1.y + e1.z * rj1.z + e1.w * rj1.w;
            #pragma unroll
            for (int o = 16; o; o >>= 1) p += __shfl_xor_sync(~0u, p, o);
            if (p > best) { best = p; bi = c; }
        }
        if (lane == 0) { wsc[wid] = best; wci[wid] = bi; }
        __syncthreads();
        if (wid == 0) {
            float v = wsc[lane]; int ci = wci[lane];
            #pragma unroll
            for (int o = 16; o; o >>= 1) {
                float ov = __shfl_down_sync(~0u, v,  o);
                int   oi = __shfl_down_sync(~0u, ci, o);
                if (ov > v || (ov == v && oi < ci)) { v = ov; ci = oi; }
            }
            if (lane == 0) { s_c = ci; s_d = 1.0f - 2.0f * v; }
        }
        __syncthreads();
        if (t == 0) { loss += s_d + s_r2; s_r2 += s_d; }
        const int cmin = s_c;
        if (t < 256) {
            float e = emb[((size_t)s * 1024 + cmin) * 256 + t];
            q[t] += e; r[t] -= e;
        }
        __syncthreads();
    }
    if (t == 0) g_loss[b] = loss;

    for (int i = t; i < 2560; i += 1024) {
        const int l = i >> 9, h = i & 511;
        float a = mod_b[l * 512 + h];
        const float* Wp = mod_W + (size_t)l * 131072 + h;
        #pragma unroll 16
        for (int d = 0; d < 256; ++d)
            a = fmaf(q[d], Wp[(size_t)d * 512], a);
        g_mods[b * 2560 + i] = a;
    }
}

// =================================================================
// Kernel 2: HMMA SIREN decoder (+ vq_loss finalize in block (0,0)).
// R15 base; TERM-MAJOR HMMA issue order (same-acc reuse distance
// 1 -> 4 instructions; per-acc FP order unchanged -> bit-identical).
// grid (64 tiles, 16 b), 256 thr, M_TILE=64, 2 CTAs/SM (128 regs).
// A planes: [64m][256k] bf16 hi/lo, pitch 528B.
// B: 16-k chunks [256n][16k] hi/lo, XOR-swizzled 32B pitch,
//    double-buffered cp.async. Single-barrier pipelined chunk loop.
// Warps 2m x 4n; warp tile 32m x 64n; 3-term Ah*Bh + Al*Bh + Ah*Bl.
// =================================================================
#define A_PITCH 528
#define A_PLANE 33792
#define B_PLANE 8192
#define B_BUF   16384

__global__ __launch_bounds__(256, 2)
void dec_mma(const float* __restrict__ coords,
             const float* __restrict__ W0g,
             const float* __restrict__ b0g,
             const float* __restrict__ bhg,
             const float* __restrict__ Wlg,
             const float* __restrict__ blg,
             float* __restrict__ out, int out_size) {
    extern __shared__ char smc[];
    char*  Ah   = smc;                         // 33792
    char*  Al   = smc + A_PLANE;               // 33792
    char*  Bb   = smc + 2 * A_PLANE;           // 32768 (2 bufs x 2 planes)
    float* w0s  = (float*)(smc + 100352);      // 768 f
    float* film = (float*)(smc + 103424);      // 768 f (gam|bet|bh, one layer)
    float* red  = (float*)(smc + 106496);      // 64*12 f
    // total 109568 B

    const int b      = blockIdx.y;
    const int m_base = blockIdx.x * 64;
    const int t  = threadIdx.x;
    const int L  = t & 31;
    const int wid = t >> 5;
    const int wm = wid >> 2;       // 0..1 (m)
    const int wn = wid & 3;        // 0..3 (n)

    // stage W0/b0
    for (int i = t; i < 768; i += 256) w0s[i] = (i < 512) ? W0g[i] : b0g[i - 512];

    // prefetch B chunk 0 (layer 0, k0) into buf 0 (swizzled dst)
    {
        #pragma unroll
        for (int j = 0; j < 4; ++j) {
            const int c = t + j * 256;          // 0..1023
            const int plane = c >> 9;
            const int cc = c & 511;
            const int r = cc >> 1, h = cc & 1;
            const unsigned char* s = g_B + plane * 131072 + r * 512 + h * 16;
            char* d = Bb + plane * B_PLANE + r * 32 + ((h * 16) ^ (((r >> 2) & 1) * 16));
            cp16(d, s);
        }
        asm volatile("cp.async.commit_group;");
    }
    __syncthreads();   // publish w0s before layer-0 fill reads it

    // ---- layer 0: fill A planes (row m = t&63, quarter q = t>>6) ----
    {
        const int m = t & 63, qd = t >> 6;
        const float2 c2 = reinterpret_cast<const float2*>(coords)[b * 4096 + m_base + m];
        char* rowH = Ah + m * A_PITCH;
        char* rowL = Al + m * A_PITCH;
        #pragma unroll 4
        for (int n = qd * 64; n < qd * 64 + 64; n += 2) {
            float p0 = fmaf(c2.x, w0s[n],     fmaf(c2.y, w0s[256 + n],     w0s[512 + n]));
            float p1 = fmaf(c2.x, w0s[n + 1], fmaf(c2.y, w0s[256 + n + 1], w0s[512 + n + 1]));
            float x0 = __sinf(30.0f * p0);
            float x1 = __sinf(30.0f * p1);
            uint32_t lo, hi = pack_split(x0, x1, lo);
            *reinterpret_cast<uint32_t*>(rowH + n * 2) = hi;
            *reinterpret_cast<uint32_t*>(rowL + n * 2) = lo;
        }
    }

    float acc[2][8][4];
    #pragma unroll
    for (int mt = 0; mt < 2; ++mt)
        #pragma unroll
        for (int nt = 0; nt < 8; ++nt)
            #pragma unroll
            for (int j = 0; j < 4; ++j) acc[mt][nt][j] = 0.f;

    // 64 iterations: 4 layers x 16 chunks of 16 k. Single barrier/chunk.
    for (int p = 0; p < 64; ++p) {
        asm volatile("cp.async.wait_group 0;");
        __syncthreads();

        if (p < 63) {      // prefetch chunk p+1 into the other buffer
            const int pl = (p + 1) >> 4, pk = (p + 1) & 15;
            const unsigned char* srcb = g_B + (size_t)pl * 262144 + pk * 32;
            char* dstb = Bb + ((p + 1) & 1) * B_BUF;
            #pragma unroll
            for (int j = 0; j < 4; ++j) {
                const int c = t + j * 256;
                const int plane = c >> 9;
                const int cc = c & 511;
                const int r = cc >> 1, h = cc & 1;
                const unsigned char* s = srcb + plane * 131072 + r * 512 + h * 16;
                char* d = dstb + plane * B_PLANE + r * 32 + ((h * 16) ^ (((r >> 2) & 1) * 16));
                cp16(d, s);
            }
            asm volatile("cp.async.commit_group;");
        }

        const int l   = p >> 4;
        const int k0g = (p & 15) * 16;

        if ((p & 15) == 15) {   // preload film (read after the mid barrier)
            for (int i = t; i < 768; i += 256)
                film[i] = (i < 512) ? g_mods[b * 2560 + 512 + l * 512 + i]
                                    : bhg[l * 256 + (i - 512)];
        }

        const char* Bbuf = Bb + (p & 1) * B_BUF;
        {
            uint32_t ah[2][4], al[2][4];
            const int acol = (k0g + (L >> 4) * 8) * 2;
            #pragma unroll
            for (int mt = 0; mt < 2; ++mt) {
                const int arow = 32 * wm + 16 * mt + (L & 15);
                ldm_x4(ah[mt], Ah + arow * A_PITCH + acol);
                ldm_x4(al[mt], Al + arow * A_PITCH + acol);
            }
            #pragma unroll
            for (int ntp = 0; ntp < 4; ++ntp) {
                uint32_t bh4[4], bl4[4];
                const int nt_sel = 2 * ntp + (L >> 4);
                const int khalf  = (L >> 3) & 1;
                const int brow   = 64 * wn + 8 * nt_sel + (L & 7);
                const unsigned boff = (unsigned)brow * 32u
                                    + ((unsigned)(khalf * 16) ^ (unsigned)(((brow >> 2) & 1) * 16));
                ldm_x4(bh4, Bbuf + boff);
                ldm_x4(bl4, Bbuf + B_PLANE + boff);
                // term-major order: same-acc reuse distance = 4 instrs
                // (per-acc FP accumulation order unchanged: ah*bh, al*bh, ah*bl)
                mma16816(acc[0][2 * ntp],     ah[0], bh4);
                mma16816(acc[1][2 * ntp],     ah[1], bh4);
                mma16816(acc[0][2 * ntp + 1], ah[0], bh4 + 2);
                mma16816(acc[1][2 * ntp + 1], ah[1], bh4 + 2);
                mma16816(acc[0][2 * ntp],     al[0], bh4);
                mma16816(acc[1][2 * ntp],     al[1], bh4);
                mma16816(acc[0][2 * ntp + 1], al[0], bh4 + 2);
                mma16816(acc[1][2 * ntp + 1], al[1], bh4 + 2);
                mma16816(acc[0][2 * ntp],     ah[0], bl4);
                mma16816(acc[1][2 * ntp],     ah[1], bl4);
                mma16816(acc[0][2 * ntp + 1], ah[0], bl4 + 2);
                mma16816(acc[1][2 * ntp + 1], ah[1], bl4 + 2);
            }
        }

        if ((p & 15) == 15) {
            __syncthreads();   // all warps done chunk-15 compute; film visible
            if (l < 3) {
                // FiLM + sin -> A planes; zero acc
                #pragma unroll
                for (int mt = 0; mt < 2; ++mt) {
                    const int r0 = 32 * wm + 16 * mt + (L >> 2);
                    #pragma unroll
                    for (int nt = 0; nt < 8; ++nt) {
                        const int n0 = 64 * wn + 8 * nt + 2 * (L & 3);
                        const float g0 = 1.0f + film[n0], g1 = 1.0f + film[n0 + 1];
                        const float e0 = film[256 + n0],  e1 = film[256 + n0 + 1];
                        const float h0 = film[512 + n0],  h1 = film[512 + n0 + 1];
                        float* a = acc[mt][nt];
                        float x00 = __sinf(30.0f * fmaf(a[0] + h0, g0, e0));
                        float x01 = __sinf(30.0f * fmaf(a[1] + h1, g1, e1));
                        float x10 = __sinf(30.0f * fmaf(a[2] + h0, g0, e0));
                        float x11 = __sinf(30.0f * fmaf(a[3] + h1, g1, e1));
                        uint32_t lo0, hi0 = pack_split(x00, x01, lo0);
                        uint32_t lo1, hi1 = pack_split(x10, x11, lo1);
                        *reinterpret_cast<uint32_t*>(Ah + r0 * A_PITCH + n0 * 2)       = hi0;
                        *reinterpret_cast<uint32_t*>(Al + r0 * A_PITCH + n0 * 2)       = lo0;
                        *reinterpret_cast<uint32_t*>(Ah + (r0 + 8) * A_PITCH + n0 * 2) = hi1;
                        *reinterpret_cast<uint32_t*>(Al + (r0 + 8) * A_PITCH + n0 * 2) = lo1;
                        a[0] = 0.f; a[1] = 0.f; a[2] = 0.f; a[3] = 0.f;
                    }
                }
                // A writes published by the single barrier at top of next chunk
            } else {
                // final layer: FiLM + sin -> output head partials
                float pacc[4][3];
                #pragma unroll
                for (int i = 0; i < 4; ++i)
                    #pragma unroll
                    for (int c = 0; c < 3; ++c) pacc[i][c] = 0.f;
                #pragma unroll
                for (int mt = 0; mt < 2; ++mt) {
                    #pragma unroll
                    for (int nt = 0; nt < 8; ++nt) {
                        const int n0 = 64 * wn + 8 * nt + 2 * (L & 3);
                        const float g0 = 1.0f + film[n0], g1 = 1.0f + film[n0 + 1];
                        const float e0 = film[256 + n0],  e1 = film[256 + n0 + 1];
                        const float h0 = film[512 + n0],  h1 = film[512 + n0 + 1];
                        float* a = acc[mt][nt];
                        float x00 = __sinf(30.0f * fmaf(a[0] + h0, g0, e0));
                        float x01 = __sinf(30.0f * fmaf(a[1] + h1, g1, e1));
                        float x10 = __sinf(30.0f * fmaf(a[2] + h0, g0, e0));
                        float x11 = __sinf(30.0f * fmaf(a[3] + h1, g1, e1));
                        #pragma unroll
                        for (int c = 0; c < 3; ++c) {
                            const float wl0 = Wlg[n0 * 3 + c];
                            const float wl1 = Wlg[(n0 + 1) * 3 + c];
                            pacc[mt * 2][c]     = fmaf(x00, wl0, fmaf(x01, wl1, pacc[mt * 2][c]));
                            pacc[mt * 2 + 1][c] = fmaf(x10, wl0, fmaf(x11, wl1, pacc[mt * 2 + 1][c]));
                        }
                    }
                }
                #pragma unroll
                for (int i = 0; i < 4; ++i)
                    #pragma unroll
                    for (int c = 0; c < 3; ++c) {
                        pacc[i][c] += __shfl_xor_sync(~0u, pacc[i][c], 1);
                        pacc[i][c] += __shfl_xor_sync(~0u, pacc[i][c], 2);
                    }
                if ((L & 3) == 0) {
                    #pragma unroll
                    for (int mt = 0; mt < 2; ++mt) {
                        const int r0 = 32 * wm + 16 * mt + (L >> 2);
                        #pragma unroll
                        for (int c = 0; c < 3; ++c) {
                            red[r0 * 12 + wn * 3 + c]       = pacc[mt * 2][c];
                            red[(r0 + 8) * 12 + wn * 3 + c] = pacc[mt * 2 + 1][c];
                        }
                    }
                }
            }
        }
    }

    __syncthreads();
    if (t < 64) {
        float* op = out + ((size_t)(b * 4096 + m_base + t)) * 3;
        #pragma unroll
        for (int c = 0; c < 3; ++c)
            op[c] = (red[t * 12 + c] + red[t * 12 + 3 + c])
                  + (red[t * 12 + 6 + c] + red[t * 12 + 9 + c]) + blg[c];
    }

    // vq_loss finalize (g_loss ready: prep_vq completed before this kernel)
    if (blockIdx.x == 0 && blockIdx.y == 0 && t == 0) {
        float s = 0.f;
        #pragma unroll
        for (int i = 0; i < 16; ++i) s += g_loss[i];
        out[out_size - 1] = s * (1.0f / 65536.0f);
    }
}

// =================================================================
extern "C" void kernel_launch(void* const* d_in, const int* in_sizes, int n_in,
                              void* d_out, int out_size) {
    const float* coords  = (const float*)d_in[0];
    const int*   lidx    = (const int*)  d_in[1];
    const float* latents = (const float*)d_in[2];
    const float* emb     = (const float*)d_in[3];
    const float* mod_W   = (const float*)d_in[4];
    const float* mod_b   = (const float*)d_in[5];
    const float* W0      = (const float*)d_in[6];
    const float* b0      = (const float*)d_in[7];
    const float* Wh      = (const float*)d_in[8];
    const float* bh      = (const float*)d_in[9];
    const float* Wl      = (const float*)d_in[10];
    const float* bl      = (const float*)d_in[11];
    float* out = (float*)d_out;

    prep_vq_kernel<<<144, 1024>>>(lidx, latents, emb, mod_W, mod_b, Wh);

    const int smem = 109568;
    cudaFuncSetAttribute(dec_mma, cudaFuncAttributeMaxDynamicSharedMemorySize, smem);
    dec_mma<<<dim3(64, 16), 256, smem>>>(coords, W0, b0, bh, Wl, bl, out, out_size);
}

// round 17
// speedup vs baseline: 1.0103x; 1.0103x over previous
#include <cuda_runtime.h>
#include <cuda_bf16.h>
#include <cstdint>

typedef unsigned long long ull;

// ---------------- scratch (no allocation allowed) ----------------
__device__ float g_mods[16 * 5 * 512];         // [b][layer][gam|bet]
__device__ float g_loss[16];                   // per-b summed loss
// transposed + bf16 hi/lo split weights:
// [layer][plane hi/lo][n=256][k=256] bf16  -> 4 * 2 * 131072 bytes
__device__ unsigned char g_B[4 * 2 * 131072];

// ---------------- helpers ----------------
__device__ __forceinline__ uint32_t smem_u32(const void* p) {
    uint32_t a;
    asm("{ .reg .u64 t; cvta.to.shared.u64 t, %1; cvt.u32.u64 %0, t; }"
        : "=r"(a) : "l"(p));
    return a;
}
__device__ __forceinline__ void cp16(void* dst, const void* src) {
    unsigned s = smem_u32(dst);
    asm volatile("cp.async.ca.shared.global [%0], [%1], 16;" :: "r"(s), "l"(src));
}
__device__ __forceinline__ void ldm_x4(uint32_t* r, const void* p) {
    uint32_t a = smem_u32(p);
    asm volatile("ldmatrix.sync.aligned.m8n8.x4.shared.b16 {%0,%1,%2,%3}, [%4];"
                 : "=r"(r[0]), "=r"(r[1]), "=r"(r[2]), "=r"(r[3]) : "r"(a));
}
__device__ __forceinline__ void mma16816(float* c, const uint32_t* a, const uint32_t* b) {
    asm volatile(
        "mma.sync.aligned.m16n8k16.row.col.f32.bf16.bf16.f32 "
        "{%0,%1,%2,%3}, {%4,%5,%6,%7}, {%8,%9}, {%0,%1,%2,%3};"
        : "+f"(c[0]), "+f"(c[1]), "+f"(c[2]), "+f"(c[3])
        : "r"(a[0]), "r"(a[1]), "r"(a[2]), "r"(a[3]), "r"(b[0]), "r"(b[1]));
}
__device__ __forceinline__ uint32_t pack_split(float x0, float x1, uint32_t& lo_out) {
    __nv_bfloat16 h0 = __float2bfloat16(x0);
    __nv_bfloat16 h1 = __float2bfloat16(x1);
    __nv_bfloat16 l0 = __float2bfloat16(x0 - __bfloat162float(h0));
    __nv_bfloat16 l1 = __float2bfloat16(x1 - __bfloat162float(h1));
    lo_out = ((uint32_t)__bfloat16_as_ushort(l1) << 16) | __bfloat16_as_ushort(l0);
    return ((uint32_t)__bfloat16_as_ushort(h1) << 16) | __bfloat16_as_ushort(h0);
}

// =================================================================
// Kernel 1: fused weight-prep (blocks 0..127) + residual VQ + FiLM
// mods (blocks 128..143). 1024 threads. VQ scan: 2 codes/iter (MLP).
// =================================================================
__global__ __launch_bounds__(1024)
void prep_vq_kernel(const int* __restrict__ lidx,
                    const float* __restrict__ latents,
                    const float* __restrict__ emb,
                    const float* __restrict__ mod_W,
                    const float* __restrict__ mod_b,
                    const float* __restrict__ Whg) {
    if (blockIdx.x < 128) {
        const int i = blockIdx.x * 1024 + threadIdx.x;   // 131072 total
        const int layer = i >> 15;
        const int kp    = (i >> 8) & 127;
        const int n     = i & 255;
        const int k     = kp * 2;
        float w0 = Whg[(size_t)layer * 65536 + (size_t)k * 256 + n];
        float w1 = Whg[(size_t)layer * 65536 + (size_t)(k + 1) * 256 + n];
        uint32_t lo, hi = pack_split(w0, w1, lo);
        unsigned char* base = g_B + (size_t)layer * 262144;
        *reinterpret_cast<uint32_t*>(base + n * 512 + k * 2)          = hi;
        *reinterpret_cast<uint32_t*>(base + 131072 + n * 512 + k * 2) = lo;
        return;
    }

    __shared__ float r[256];
    __shared__ float q[256];
    __shared__ float wsc[32];
    __shared__ int   wci[32];
    __shared__ float s_d, s_r2;
    __shared__ int   s_c;

    const int b = blockIdx.x - 128, t = threadIdx.x;
    const int lane = t & 31, wid = t >> 5;

    if (t < 256) {
        const float* lp = latents + (size_t)lidx[b] * 1024;
        float z = lp[t] + lp[256 + t] + lp[512 + t] + lp[768 + t];
        r[t] = z; q[t] = 0.f;
    }
    __syncthreads();

    if (wid == 0) {
        float rz = 0.f;
        #pragma unroll
        for (int j = 0; j < 8; ++j) { float v = r[lane * 8 + j]; rz = fmaf(v, v, rz); }
        #pragma unroll
        for (int o = 16; o; o >>= 1) rz += __shfl_xor_sync(~0u, rz, o);
        if (lane == 0) s_r2 = rz;
    }
    float loss = 0.f;
    __syncthreads();

    for (int s = 0; s < 4; ++s) {
        float4 rj0 = reinterpret_cast<const float4*>(r)[lane * 2];
        float4 rj1 = reinterpret_cast<const float4*>(r)[lane * 2 + 1];
        float best = -3.4e38f;
        int   bi   = 0;
        const int c0 = wid * 32;
        #pragma unroll 4
        for (int i = 0; i < 32; i += 2) {   // two codes per iter (2x MLP)
            const int c = c0 + i;
            const float4* Ea = reinterpret_cast<const float4*>(emb)
                               + (size_t)(s * 1024 + c) * 64 + lane * 2;
            const float4* Eb = Ea + 64;     // code c+1
            float4 e0 = Ea[0], e1 = Ea[1];
            float4 f0 = Eb[0], f1 = Eb[1];
            float pa = e0.x * rj0.x + e0.y * rj0.y + e0.z * rj0.z + e0.w * rj0.w
                     + e1.x * rj1.x + e1.y * rj1.y + e1.z * rj1.z + e1.w * rj1.w;
            float pb = f0.x * rj0.x + f0.y * rj0.y + f0.z * rj0.z + f0.w * rj0.w
                     + f1.x * rj1.x + f1.y * rj1.y + f1.z * rj1.z + f1.w * rj1.w;
            #pragma unroll
            for (int o = 16; o; o >>= 1) {
                pa += __shfl_xor_sync(~0u, pa, o);
                pb += __shfl_xor_sync(~0u, pb, o);
            }
            if (pa > best) { best = pa; bi = c; }
            if (pb > best) { best = pb; bi = c + 1; }
        }
        if (lane == 0) { wsc[wid] = best; wci[wid] = bi; }
        __syncthreads();
        if (wid == 0) {
            float v = wsc[lane]; int ci = wci[lane];
            #pragma unroll
            for (int o = 16; o; o >>= 1) {
                float ov = __shfl_down_sync(~0u, v,  o);
                int   oi = __shfl_down_sync(~0u, ci, o);
                if (ov > v || (ov == v && oi < ci)) { v = ov; ci = oi; }
            }
            if (lane == 0) { s_c = ci; s_d = 1.0f - 2.0f * v; }
        }
        __syncthreads();
        if (t == 0) { loss += s_d + s_r2; s_r2 += s_d; }
        const int cmin = s_c;
        if (t < 256) {
            float e = emb[((size_t)s * 1024 + cmin) * 256 + t];
            q[t] += e; r[t] -= e;
        }
        __syncthreads();
    }
    if (t == 0) g_loss[b] = loss;

    for (int i = t; i < 2560; i += 1024) {
        const int l = i >> 9, h = i & 511;
        float a = mod_b[l * 512 + h];
        const float* Wp = mod_W + (size_t)l * 131072 + h;
        #pragma unroll 16
        for (int d = 0; d < 256; ++d)
            a = fmaf(q[d], Wp[(size_t)d * 512], a);
        g_mods[b * 2560 + i] = a;
    }
}

// =================================================================
// Kernel 2: HMMA SIREN decoder (+ vq_loss finalize in block (0,0)).
// R16 base; B-FRAGMENT REGISTER PING-PONG: ntp+1's LDSM issued
// before ntp's MMAs (LDSM->consume distance ~2 -> ~14 instrs),
// overlapping crossbar and tensor pipes within each warp.
// grid (64 tiles, 16 b), 256 thr, M_TILE=64, 2 CTAs/SM (128 regs).
// A planes: [64m][256k] bf16 hi/lo, pitch 528B.
// B: 16-k chunks [256n][16k] hi/lo, XOR-swizzled 32B pitch,
//    double-buffered cp.async. Single-barrier pipelined chunk loop.
// Warps 2m x 4n; warp tile 32m x 64n; 3-term Ah*Bh + Al*Bh + Ah*Bl.
// =================================================================
#define A_PITCH 528
#define A_PLANE 33792
#define B_PLANE 8192
#define B_BUF   16384

__global__ __launch_bounds__(256, 2)
void dec_mma(const float* __restrict__ coords,
             const float* __restrict__ W0g,
             const float* __restrict__ b0g,
             const float* __restrict__ bhg,
             const float* __restrict__ Wlg,
             const float* __restrict__ blg,
             float* __restrict__ out, int out_size) {
    extern __shared__ char smc[];
    char*  Ah   = smc;                         // 33792
    char*  Al   = smc + A_PLANE;               // 33792
    char*  Bb   = smc + 2 * A_PLANE;           // 32768 (2 bufs x 2 planes)
    float* w0s  = (float*)(smc + 100352);      // 768 f
    float* film = (float*)(smc + 103424);      // 768 f (gam|bet|bh, one layer)
    float* red  = (float*)(smc + 106496);      // 64*12 f
    // total 109568 B

    const int b      = blockIdx.y;
    const int m_base = blockIdx.x * 64;
    const int t  = threadIdx.x;
    const int L  = t & 31;
    const int wid = t >> 5;
    const int wm = wid >> 2;       // 0..1 (m)
    const int wn = wid & 3;        // 0..3 (n)

    // stage W0/b0
    for (int i = t; i < 768; i += 256) w0s[i] = (i < 512) ? W0g[i] : b0g[i - 512];

    // prefetch B chunk 0 (layer 0, k0) into buf 0 (swizzled dst)
    {
        #pragma unroll
        for (int j = 0; j < 4; ++j) {
            const int c = t + j * 256;          // 0..1023
            const int plane = c >> 9;
            const int cc = c & 511;
            const int r = cc >> 1, h = cc & 1;
            const unsigned char* s = g_B + plane * 131072 + r * 512 + h * 16;
            char* d = Bb + plane * B_PLANE + r * 32 + ((h * 16) ^ (((r >> 2) & 1) * 16));
            cp16(d, s);
        }
        asm volatile("cp.async.commit_group;");
    }
    __syncthreads();   // publish w0s before layer-0 fill reads it

    // ---- layer 0: fill A planes (row m = t&63, quarter q = t>>6) ----
    {
        const int m = t & 63, qd = t >> 6;
        const float2 c2 = reinterpret_cast<const float2*>(coords)[b * 4096 + m_base + m];
        char* rowH = Ah + m * A_PITCH;
        char* rowL = Al + m * A_PITCH;
        #pragma unroll 4
        for (int n = qd * 64; n < qd * 64 + 64; n += 2) {
            float p0 = fmaf(c2.x, w0s[n],     fmaf(c2.y, w0s[256 + n],     w0s[512 + n]));
            float p1 = fmaf(c2.x, w0s[n + 1], fmaf(c2.y, w0s[256 + n + 1], w0s[512 + n + 1]));
            float x0 = __sinf(30.0f * p0);
            float x1 = __sinf(30.0f * p1);
            uint32_t lo, hi = pack_split(x0, x1, lo);
            *reinterpret_cast<uint32_t*>(rowH + n * 2) = hi;
            *reinterpret_cast<uint32_t*>(rowL + n * 2) = lo;
        }
    }

    float acc[2][8][4];
    #pragma unroll
    for (int mt = 0; mt < 2; ++mt)
        #pragma unroll
        for (int nt = 0; nt < 8; ++nt)
            #pragma unroll
            for (int j = 0; j < 4; ++j) acc[mt][nt][j] = 0.f;

    // 64 iterations: 4 layers x 16 chunks of 16 k. Single barrier/chunk.
    for (int p = 0; p < 64; ++p) {
        asm volatile("cp.async.wait_group 0;");
        __syncthreads();

        if (p < 63) {      // prefetch chunk p+1 into the other buffer
            const int pl = (p + 1) >> 4, pk = (p + 1) & 15;
            const unsigned char* srcb = g_B + (size_t)pl * 262144 + pk * 32;
            char* dstb = Bb + ((p + 1) & 1) * B_BUF;
            #pragma unroll
            for (int j = 0; j < 4; ++j) {
                const int c = t + j * 256;
                const int plane = c >> 9;
                const int cc = c & 511;
                const int r = cc >> 1, h = cc & 1;
                const unsigned char* s = srcb + plane * 131072 + r * 512 + h * 16;
                char* d = dstb + plane * B_PLANE + r * 32 + ((h * 16) ^ (((r >> 2) & 1) * 16));
                cp16(d, s);
            }
            asm volatile("cp.async.commit_group;");
        }

        const int l   = p >> 4;
        const int k0g = (p & 15) * 16;

        if ((p & 15) == 15) {   // preload film (read after the mid barrier)
            for (int i = t; i < 768; i += 256)
                film[i] = (i < 512) ? g_mods[b * 2560 + 512 + l * 512 + i]
                                    : bhg[l * 256 + (i - 512)];
        }

        const char* Bbuf = Bb + (p & 1) * B_BUF;
        {
            uint32_t ah[2][4], al[2][4];
            const int acol = (k0g + (L >> 4) * 8) * 2;
            #pragma unroll
            for (int mt = 0; mt < 2; ++mt) {
                const int arow = 32 * wm + 16 * mt + (L & 15);
                ldm_x4(ah[mt], Ah + arow * A_PITCH + acol);
                ldm_x4(al[mt], Al + arow * A_PITCH + acol);
            }
            // B-frag ping-pong: base offset for this lane (ntp stride = 512B)
            const int nt0  = (L >> 4);
            const int khalf = (L >> 3) & 1;
            const int brow0 = 64 * wn + 8 * nt0 + (L & 7);
            const unsigned boff0 = (unsigned)brow0 * 32u
                                 + ((unsigned)(khalf * 16) ^ (unsigned)(((brow0 >> 2) & 1) * 16));
            uint32_t bh[2][4], bl[2][4];
            ldm_x4(bh[0], Bbuf + boff0);
            ldm_x4(bl[0], Bbuf + B_PLANE + boff0);
            #pragma unroll
            for (int ntp = 0; ntp < 4; ++ntp) {
                const int cur = ntp & 1, nxt = cur ^ 1;
                if (ntp < 3) {   // prefetch next ntp's B frags BEFORE MMAs
                    const unsigned bo = boff0 + (unsigned)(ntp + 1) * 512u;
                    ldm_x4(bh[nxt], Bbuf + bo);
                    ldm_x4(bl[nxt], Bbuf + B_PLANE + bo);
                }
                // term-major MMAs on current frags
                mma16816(acc[0][2 * ntp],     ah[0], bh[cur]);
                mma16816(acc[1][2 * ntp],     ah[1], bh[cur]);
                mma16816(acc[0][2 * ntp + 1], ah[0], bh[cur] + 2);
                mma16816(acc[1][2 * ntp + 1], ah[1], bh[cur] + 2);
                mma16816(acc[0][2 * ntp],     al[0], bh[cur]);
                mma16816(acc[1][2 * ntp],     al[1], bh[cur]);
                mma16816(acc[0][2 * ntp + 1], al[0], bh[cur] + 2);
                mma16816(acc[1][2 * ntp + 1], al[1], bh[cur] + 2);
                mma16816(acc[0][2 * ntp],     ah[0], bl[cur]);
                mma16816(acc[1][2 * ntp],     ah[1], bl[cur]);
                mma16816(acc[0][2 * ntp + 1], ah[0], bl[cur] + 2);
                mma16816(acc[1][2 * ntp + 1], ah[1], bl[cur] + 2);
            }
        }

        if ((p & 15) == 15) {
            __syncthreads();   // all warps done chunk-15 compute; film visible
            if (l < 3) {
                // FiLM + sin -> A planes; zero acc
                #pragma unroll
                for (int mt = 0; mt < 2; ++mt) {
                    const int r0 = 32 * wm + 16 * mt + (L >> 2);
                    #pragma unroll
                    for (int nt = 0; nt < 8; ++nt) {
                        const int n0 = 64 * wn + 8 * nt + 2 * (L & 3);
                        const float g0 = 1.0f + film[n0], g1 = 1.0f + film[n0 + 1];
                        const float e0 = film[256 + n0],  e1 = film[256 + n0 + 1];
                        const float h0 = film[512 + n0],  h1 = film[512 + n0 + 1];
                        float* a = acc[mt][nt];
                        float x00 = __sinf(30.0f * fmaf(a[0] + h0, g0, e0));
                        float x01 = __sinf(30.0f * fmaf(a[1] + h1, g1, e1));
                        float x10 = __sinf(30.0f * fmaf(a[2] + h0, g0, e0));
                        float x11 = __sinf(30.0f * fmaf(a[3] + h1, g1, e1));
                        uint32_t lo0, hi0 = pack_split(x00, x01, lo0);
                        uint32_t lo1, hi1 = pack_split(x10, x11, lo1);
                        *reinterpret_cast<uint32_t*>(Ah + r0 * A_PITCH + n0 * 2)       = hi0;
                        *reinterpret_cast<uint32_t*>(Al + r0 * A_PITCH + n0 * 2)       = lo0;
                        *reinterpret_cast<uint32_t*>(Ah + (r0 + 8) * A_PITCH + n0 * 2) = hi1;
                        *reinterpret_cast<uint32_t*>(Al + (r0 + 8) * A_PITCH + n0 * 2) = lo1;
                        a[0] = 0.f; a[1] = 0.f; a[2] = 0.f; a[3] = 0.f;
                    }
                }
                // A writes published by the single barrier at top of next chunk
            } else {
                // final layer: FiLM + sin -> output head partials
                float pacc[4][3];
                #pragma unroll
                for (int i = 0; i < 4; ++i)
                    #pragma unroll
                    for (int c = 0; c < 3; ++c) pacc[i][c] = 0.f;
                #pragma unroll
                for (int mt = 0; mt < 2; ++mt) {
                    #pragma unroll
                    for (int nt = 0; nt < 8; ++nt) {
                        const int n0 = 64 * wn + 8 * nt + 2 * (L & 3);
                        const float g0 = 1.0f + film[n0], g1 = 1.0f + film[n0 + 1];
                        const float e0 = film[256 + n0],  e1 = film[256 + n0 + 1];
                        const float h0 = film[512 + n0],  h1 = film[512 + n0 + 1];
                        float* a = acc[mt][nt];
                        float x00 = __sinf(30.0f * fmaf(a[0] + h0, g0, e0));
                        float x01 = __sinf(30.0f * fmaf(a[1] + h1, g1, e1));
                        float x10 = __sinf(30.0f * fmaf(a[2] + h0, g0, e0));
                        float x11 = __sinf(30.0f * fmaf(a[3] + h1, g1, e1));
                        #pragma unroll
                        for (int c = 0; c < 3; ++c) {
                            const float wl0 = Wlg[n0 * 3 + c];
                            const float wl1 = Wlg[(n0 + 1) * 3 + c];
                            pacc[mt * 2][c]     = fmaf(x00, wl0, fmaf(x01, wl1, pacc[mt * 2][c]));
                            pacc[mt * 2 + 1][c] = fmaf(x10, wl0, fmaf(x11, wl1, pacc[mt * 2 + 1][c]));
                        }
                    }
                }
                #pragma unroll
                for (int i = 0; i < 4; ++i)
                    #pragma unroll
                    for (int c = 0; c < 3; ++c) {
                        pacc[i][c] += __shfl_xor_sync(~0u, pacc[i][c], 1);
                        pacc[i][c] += __shfl_xor_sync(~0u, pacc[i][c], 2);
                    }
                if ((L & 3) == 0) {
                    #pragma unroll
                    for (int mt = 0; mt < 2; ++mt) {
                        const int r0 = 32 * wm + 16 * mt + (L >> 2);
                        #pragma unroll
                        for (int c = 0; c < 3; ++c) {
                            red[r0 * 12 + wn * 3 + c]       = pacc[mt * 2][c];
                            red[(r0 + 8) * 12 + wn * 3 + c] = pacc[mt * 2 + 1][c];
                        }
                    }
                }
            }
        }
    }

    __syncthreads();
    if (t < 64) {
        float* op = out + ((size_t)(b * 4096 + m_base + t)) * 3;
        #pragma unroll
        for (int c = 0; c < 3; ++c)
            op[c] = (red[t * 12 + c] + red[t * 12 + 3 + c])
                  + (red[t * 12 + 6 + c] + red[t * 12 + 9 + c]) + blg[c];
    }

    // vq_loss finalize (g_loss ready: prep_vq completed before this kernel)
    if (blockIdx.x == 0 && blockIdx.y == 0 && t == 0) {
        float s = 0.f;
        #pragma unroll
        for (int i = 0; i < 16; ++i) s += g_loss[i];
        out[out_size - 1] = s * (1.0f / 65536.0f);
    }
}

// =================================================================
extern "C" void kernel_launch(void* const* d_in, const int* in_sizes, int n_in,
                              void* d_out, int out_size) {
    const float* coords  = (const float*)d_in[0];
    const int*   lidx    = (const int*)  d_in[1];
    const float* latents = (const float*)d_in[2];
    const float* emb     = (const float*)d_in[3];
    const float* mod_W   = (const float*)d_in[4];
    const float* mod_b   = (const float*)d_in[5];
    const float* W0      = (const float*)d_in[6];
    const float* b0      = (const float*)d_in[7];
    const float* Wh      = (const float*)d_in[8];
    const float* bh      = (const float*)d_in[9];
    const float* Wl      = (const float*)d_in[10];
    const float* bl      = (const float*)d_in[11];
    float* out = (float*)d_out;

    prep_vq_kernel<<<144, 1024>>>(lidx, latents, emb, mod_W, mod_b, Wh);

    const int smem = 109568;
    cudaFuncSetAttribute(dec_mma, cudaFuncAttributeMaxDynamicSharedMemorySize, smem);
    dec_mma<<<dim3(64, 16), 256, smem>>>(coords, W0, b0, bh, Wl, bl, out, out_size);
}